// round 5
// baseline (speedup 1.0000x reference)
#include <cuda_runtime.h>
#include <math.h>
#include <stdint.h>

#define cB 4
#define cL 512
#define cD 512
#define cH 16
#define cKH 32
#define cFF 2048
#define cNL 8
#define cND 14
#define cM 512
#define cBL (cB*cL)
#define SCALEF 0.17677669529663687f  // 1/sqrt(32)

// ------------------------- scratch (static device globals) ------------------
__device__ float g_h [cBL*cD];
__device__ float g_q [cBL*cD];
__device__ float g_k [cBL*cD];
__device__ float g_v [cBL*cD];
__device__ float g_z [cBL*cD];
__device__ float g_o [cBL*cD];
__device__ float g_h2[cBL*cD];
__device__ float g_f [cBL*cFF];
__device__ float g_qE [cB*cH*cL*cND];
__device__ float g_kE [cB*cH*cL*cND];
__device__ unsigned char g_didx[cB*cL*cL];
__device__ float g_Vsum[cND*cKH];
__device__ float g_sumKkr[cND];

// ------------------------- helpers ------------------------------------------
__device__ __forceinline__ uint32_t tf32r(float x) {
    uint32_t r;
    asm("cvt.rna.tf32.f32 %0, %1;" : "=r"(r) : "f"(x));
    return r;
}
__device__ __forceinline__ void mma_tf32(float* c, const uint32_t* a, const uint32_t* b) {
    asm volatile(
        "mma.sync.aligned.m16n8k8.row.col.f32.tf32.tf32.f32 "
        "{%0,%1,%2,%3}, {%4,%5,%6,%7}, {%8,%9}, {%0,%1,%2,%3};\n"
        : "+f"(c[0]), "+f"(c[1]), "+f"(c[2]), "+f"(c[3])
        : "r"(a[0]), "r"(a[1]), "r"(a[2]), "r"(a[3]), "r"(b[0]), "r"(b[1]));
}

// ------------------------- 3xTF32 tensor-core GEMM --------------------------
// C[M,N] = A[M,K] @ W[K,N] + bias (opt exact GELU). CTA tile 128x128, BK=32.
// SMEM holds hi/lo tf32 splits pre-permuted into mma fragment order:
//   A: [ks(4)][mt(8)][lane(32)][q(4)]   B: [ks(4)][nt(16)][lane(32)][q(2)]
struct GArgs {
    const float* A;
    const float* W0; const float* W1; const float* W2;
    const float* c0; const float* c1; const float* c2;
    float* C0; float* C1; float* C2;
};

#define GSM_BYTES (4 * 4096 * 4)

template<bool GELU, bool TRIPLE>
__global__ __launch_bounds__(256) void mma_gemm(GArgs args, int Md, int Nd, int Kd) {
    extern __shared__ float smem[];
    float* sAh = smem;
    float* sAl = smem + 4096;
    float* sBh = smem + 8192;
    float* sBl = smem + 12288;

    int t = threadIdx.x;
    const float* A = args.A;
    const float* W; const float* bias; float* C;
    if (TRIPLE) {
        int z = blockIdx.z;
        W    = (z == 0) ? args.W0 : (z == 1) ? args.W1 : args.W2;
        bias = (z == 0) ? args.c0 : (z == 1) ? args.c1 : args.c2;
        C    = (z == 0) ? args.C0 : (z == 1) ? args.C1 : args.C2;
    } else { W = args.W0; bias = args.c0; C = args.C0; }

    int m0 = blockIdx.y * 128, n0 = blockIdx.x * 128;

    // --- copy-index precompute ---
    int am = t & 127;            // A row within tile
    int ah_half = t >> 7;        // which 16-k half
    int bkr = t & 31;            // B k-row within chunk
    int bg  = t >> 5;            // B 16-col group

    float4 aReg[4], bReg[4];
    auto loadG = [&](int k0) {
#pragma unroll
        for (int j = 0; j < 4; j++)
            aReg[j] = *(const float4*)&A[(size_t)(m0 + am) * Kd + k0 + ah_half * 16 + j * 4];
#pragma unroll
        for (int j = 0; j < 4; j++)
            bReg[j] = *(const float4*)&W[(size_t)(k0 + bkr) * Nd + n0 + bg * 16 + j * 4];
    };
    auto storeS = [&]() {
        int mt = am >> 4;
        int rlo = (am & 7) << 2, rq = (am >> 3) & 1;
#pragma unroll
        for (int j = 0; j < 4; j++) {
            const float* pv = &aReg[j].x;
#pragma unroll
            for (int e = 0; e < 4; e++) {
                int k = ah_half * 16 + j * 4 + e;
                int ks = k >> 3, kc = k & 7;
                int lane = rlo | (kc & 3);
                int q = rq + ((kc >> 2) << 1);
                int idx = (((ks << 3) + mt) << 7) + (lane << 2) + q;
                float v = pv[e];
                uint32_t hi = tf32r(v);
                float lo = v - __uint_as_float(hi);
                sAh[idx] = __uint_as_float(hi);
                sAl[idx] = __uint_as_float(tf32r(lo));
            }
        }
        int ks = bkr >> 3, kc = bkr & 7;
        int lb = kc & 3, q = kc >> 2;
#pragma unroll
        for (int j = 0; j < 4; j++) {
            const float* pv = &bReg[j].x;
#pragma unroll
            for (int e = 0; e < 4; e++) {
                int n = bg * 16 + j * 4 + e;
                int nt = n >> 3, nc = n & 7;
                int idx = (((ks << 4) + nt) << 6) + (((nc << 2) | lb) << 1) + q;
                float v = pv[e];
                uint32_t hi = tf32r(v);
                float lo = v - __uint_as_float(hi);
                sBh[idx] = __uint_as_float(hi);
                sBl[idx] = __uint_as_float(tf32r(lo));
            }
        }
    };

    int lane = t & 31, wid = t >> 5;
    int wm = wid & 3, wn = wid >> 2;

    float c[2][8][4];
#pragma unroll
    for (int i = 0; i < 2; i++)
#pragma unroll
        for (int j = 0; j < 8; j++)
#pragma unroll
            for (int q = 0; q < 4; q++) c[i][j][q] = 0.f;

    loadG(0); storeS();
    __syncthreads();

    int nchunks = Kd >> 5;
    for (int ch = 0; ch < nchunks; ch++) {
        bool more = (ch + 1 < nchunks);
        if (more) loadG((ch + 1) << 5);
#pragma unroll
        for (int ks = 0; ks < 4; ks++) {
            uint32_t a_h[2][4], a_l[2][4];
#pragma unroll
            for (int i = 0; i < 2; i++) {
                int base = (((ks << 3) + wm * 2 + i) << 7) + (lane << 2);
                *(uint4*)a_h[i] = *(const uint4*)&sAh[base];
                *(uint4*)a_l[i] = *(const uint4*)&sAl[base];
            }
#pragma unroll
            for (int j = 0; j < 8; j++) {
                int base = (((ks << 4) + wn * 8 + j) << 6) + (lane << 1);
                uint32_t b_h[2], b_l[2];
                *(uint2*)b_h = *(const uint2*)&sBh[base];
                *(uint2*)b_l = *(const uint2*)&sBl[base];
#pragma unroll
                for (int i = 0; i < 2; i++) {
                    mma_tf32(c[i][j], a_l[i], b_h);
                    mma_tf32(c[i][j], a_h[i], b_l);
                    mma_tf32(c[i][j], a_h[i], b_h);
                }
            }
        }
        if (more) {
            __syncthreads();
            storeS();
            __syncthreads();
        }
    }

    // --- epilogue ---
    int gr = lane >> 2, t4 = lane & 3;
#pragma unroll
    for (int i = 0; i < 2; i++) {
        int rb = m0 + wm * 32 + i * 16 + gr;
#pragma unroll
        for (int j = 0; j < 8; j++) {
            int col = n0 + wn * 64 + j * 8 + t4 * 2;
            float2 bb = *(const float2*)&bias[col];
            float v0 = c[i][j][0] + bb.x, v1 = c[i][j][1] + bb.y;
            float v2 = c[i][j][2] + bb.x, v3 = c[i][j][3] + bb.y;
            if (GELU) {
                v0 = 0.5f * v0 * (1.0f + erff(v0 * 0.70710678118654752f));
                v1 = 0.5f * v1 * (1.0f + erff(v1 * 0.70710678118654752f));
                v2 = 0.5f * v2 * (1.0f + erff(v2 * 0.70710678118654752f));
                v3 = 0.5f * v3 * (1.0f + erff(v3 * 0.70710678118654752f));
            }
            *(float2*)&C[(size_t)rb * Nd + col] = make_float2(v0, v1);
            *(float2*)&C[(size_t)(rb + 8) * Nd + col] = make_float2(v2, v3);
        }
    }
}

// ------------------------- distance bucketize -------------------------------
__global__ void didx_kernel(const float* __restrict__ dist) {
    int i = blockIdx.x * blockDim.x + threadIdx.x;
    float d = dist[i];
    int idx = 0;
#pragma unroll
    for (int j = 1; j <= 14; j++) idx += (10.0f * (float)j < d) ? 1 : 0;
    if (idx > 13) idx = 13;
    g_didx[i] = (unsigned char)idx;
}

// ------------------------- embedding gather ---------------------------------
__global__ void embed_kernel(const int* __restrict__ ct, const float* __restrict__ emb) {
    int row = blockIdx.x;
    int c0  = ct[row];
    for (int c = threadIdx.x; c < cD; c += blockDim.x)
        g_h[(size_t)row * cD + c] = emb[(size_t)c0 * cD + c];
}

// ------------------------- tiny precompute ----------------------------------
__global__ void prep_kernel(const float* __restrict__ Kkr,
                            const float* __restrict__ Vqk,
                            const float* __restrict__ Vqr,
                            const float* __restrict__ Vkr) {
    int t = threadIdx.x;
    if (t < cND * cKH) g_Vsum[t] = Vqk[t] + Vqr[t] + Vkr[t];
    if (t < cND) {
        float s = 0.f;
        for (int k = 0; k < cKH; k++) s += Kkr[t * cKH + k];
        g_sumKkr[t] = s;
    }
}

// ------------------------- qE / kE ------------------------------------------
__global__ void qke_kernel(const float* __restrict__ Kqk, const float* __restrict__ Kqr) {
    __shared__ float sq[cD], sk[cD];
    __shared__ float sKa[cND * cKH], sKb[cND * cKH];
    int bl = blockIdx.x;
    int t  = threadIdx.x;
    for (int c = t; c < cD; c += 256) {
        sq[c] = g_q[(size_t)bl * cD + c];
        sk[c] = g_k[(size_t)bl * cD + c];
    }
    for (int c = t; c < cND * cKH; c += 256) { sKa[c] = Kqk[c]; sKb[c] = Kqr[c]; }
    __syncthreads();
    if (t < cH * cND) {
        int h = t / cND, d = t % cND;
        float s1 = 0.f, s2 = 0.f;
#pragma unroll
        for (int k = 0; k < cKH; k++) {
            s1 += sq[h * cKH + k] * sKa[d * cKH + k];
            s2 += sk[h * cKH + k] * sKb[d * cKH + k];
        }
        int b = bl / cL, l = bl % cL;
        size_t off = ((size_t)(b * cH + (size_t)h) * cL + l) * cND + d;
        g_qE[off] = s1;
        g_kE[off] = s2;
    }
}

// ------------------------- fused flash attention ----------------------------
#define SC_STRIDE 520
__global__ __launch_bounds__(256) void flash_attn_kernel() {
    extern __shared__ char smraw[];
    float* SC            = (float*)smraw;
    unsigned char* DIDX  = (unsigned char*)(SC + 64 * SC_STRIDE);
    float* QS   = (float*)(DIDX + 64 * 512);
    float* KS   = QS + 32 * 65;
    float* QES  = KS + 2112;
    float* KES  = QES + 64 * 16;
    float* HIST = KES + 64 * 16;
    float* REDM = HIST + 16 * 256;
    float* REDS = REDM + 256;
    float* RINV = REDS + 256;
    float* VSUM = RINV + 64;
    float* SKR  = VSUM + 448;

    int bh = blockIdx.y;
    int b  = bh >> 4, h = bh & 15;
    int l0 = blockIdx.x * 64;
    int t  = threadIdx.x;

#pragma unroll
    for (int r = 0; r < 8; r++) {
        int l = r * 8 + (t >> 5), k = t & 31;
        QS[k * 65 + l] = g_q[(size_t)(b * cL + l0 + l) * cD + h * 32 + k];
    }
    for (int idx = t; idx < 64 * cND; idx += 256) {
        int l = idx / cND, d = idx % cND;
        QES[l * 16 + d] = g_qE[((size_t)bh * cL + l0 + l) * cND + d];
    }
    {
        const int4* src = (const int4*)(g_didx + ((size_t)b * cL + l0) * cL);
        for (int idx = t; idx < 2048; idx += 256) ((int4*)DIDX)[idx] = src[idx];
    }
    for (int idx = t; idx < cND * 32; idx += 256) VSUM[idx] = g_Vsum[idx];
    if (t < cND) SKR[t] = g_sumKkr[t];
    __syncthreads();

    {
        int tx = t & 15, ty = t >> 4;
        for (int xt = 0; xt < 8; xt++) {
            int x0 = xt * 64;
#pragma unroll
            for (int r = 0; r < 8; r++) {
                int i = r * 8 + (t >> 5), k = t & 31;
                KS[k * 65 + i] = g_k[(size_t)(b * cL + x0 + i) * cD + h * 32 + k];
            }
            for (int idx = t; idx < 64 * cND; idx += 256) {
                int i2 = idx / cND, d = idx % cND;
                KES[i2 * 16 + d] = g_kE[((size_t)bh * cL + x0 + i2) * cND + d];
            }
            __syncthreads();
            float acc[4][4] = {};
#pragma unroll
            for (int k = 0; k < 32; k++) {
                float a[4], bb[4];
#pragma unroll
                for (int i = 0; i < 4; i++) a[i] = QS[k * 65 + ty + 16 * i];
#pragma unroll
                for (int j = 0; j < 4; j++) bb[j] = KS[k * 65 + tx + 16 * j];
#pragma unroll
                for (int i = 0; i < 4; i++)
#pragma unroll
                    for (int j = 0; j < 4; j++) acc[i][j] += a[i] * bb[j];
            }
#pragma unroll
            for (int i = 0; i < 4; i++)
#pragma unroll
                for (int j = 0; j < 4; j++) {
                    int li = ty + 16 * i, xj = tx + 16 * j;
                    int d = DIDX[li * 512 + x0 + xj];
                    SC[li * SC_STRIDE + x0 + xj] =
                        (acc[i][j] + QES[li * 16 + d] + KES[xj * 16 + d] + SKR[d]) * SCALEF;
                }
            __syncthreads();
        }
    }

    {
        int r = t >> 2, j = t & 3;
        float m = -1e30f;
        for (int i = 0; i < 128; i++) m = fmaxf(m, SC[r * SC_STRIDE + 4 * i + j]);
        REDM[t] = m;
        __syncthreads();
        m = fmaxf(fmaxf(REDM[r * 4], REDM[r * 4 + 1]), fmaxf(REDM[r * 4 + 2], REDM[r * 4 + 3]));
#pragma unroll
        for (int d = 0; d < 16; d++) HIST[d * 256 + t] = 0.f;
        float s = 0.f;
        for (int i = 0; i < 128; i++) {
            int x = 4 * i + j;
            float p = __expf(SC[r * SC_STRIDE + x] - m);
            SC[r * SC_STRIDE + x] = p;
            s += p;
            int d = DIDX[r * 512 + x];
            HIST[d * 256 + t] += p;
        }
        REDS[t] = s;
        __syncthreads();
        if (t < 64) RINV[t] = 1.0f / (REDS[4 * t] + REDS[4 * t + 1] + REDS[4 * t + 2] + REDS[4 * t + 3]);
        for (int idx = t; idx < 64 * cND; idx += 256) {
            int d = idx >> 6, r2 = idx & 63;
            QES[r2 * 16 + d] = HIST[d * 256 + 4 * r2]     + HIST[d * 256 + 4 * r2 + 1]
                             + HIST[d * 256 + 4 * r2 + 2] + HIST[d * 256 + 4 * r2 + 3];
        }
        __syncthreads();
    }

    {
        int txk = t & 31, tyr = t >> 5;
        float acc[8] = {};
        float* VS = KS;
        for (int xt = 0; xt < 8; xt++) {
            int x0 = xt * 64;
#pragma unroll
            for (int r = 0; r < 8; r++) {
                int i = r * 8 + tyr;
                VS[i * 33 + txk] = g_v[(size_t)(b * cL + x0 + i) * cD + h * 32 + txk];
            }
            __syncthreads();
#pragma unroll
            for (int xc = 0; xc < 16; xc++) {
                float4 a4[8];
#pragma unroll
                for (int i = 0; i < 8; i++)
                    a4[i] = *(const float4*)&SC[(i * 8 + tyr) * SC_STRIDE + x0 + xc * 4];
#pragma unroll
                for (int q = 0; q < 4; q++) {
                    float vb = VS[(xc * 4 + q) * 33 + txk];
                    const float* pa;
#pragma unroll
                    for (int i = 0; i < 8; i++) {
                        pa = &a4[i].x;
                        acc[i] += pa[q] * vb;
                    }
                }
            }
            __syncthreads();
        }
#pragma unroll
        for (int i = 0; i < 8; i++) {
            int l = i * 8 + tyr;
            float zv = acc[i];
#pragma unroll
            for (int d = 0; d < cND; d++) zv += QES[l * 16 + d] * VSUM[d * 32 + txk];
            g_z[(size_t)(b * cL + l0 + l) * cD + h * 32 + txk] = zv * RINV[l];
        }
    }
}

// ------------------------- layernorm of (X + R) -----------------------------
__global__ void ln_kernel(const float* __restrict__ X, const float* __restrict__ R,
                          const float* __restrict__ gg, const float* __restrict__ bb,
                          float* __restrict__ out) {
    int row = blockIdx.x, t = threadIdx.x;
    float lv[4];
    float s = 0.f;
#pragma unroll
    for (int r = 0; r < 4; r++) {
        int c = t + 128 * r;
        lv[r] = X[(size_t)row * cD + c] + R[(size_t)row * cD + c];
        s += lv[r];
    }
    __shared__ float red[128];
    red[t] = s; __syncthreads();
#pragma unroll
    for (int st = 64; st > 0; st >>= 1) { if (t < st) red[t] += red[t + st]; __syncthreads(); }
    float mu = red[0] * (1.0f / cD);
    __syncthreads();
    float vs = 0.f;
#pragma unroll
    for (int r = 0; r < 4; r++) { float d = lv[r] - mu; vs += d * d; }
    red[t] = vs; __syncthreads();
#pragma unroll
    for (int st = 64; st > 0; st >>= 1) { if (t < st) red[t] += red[t + st]; __syncthreads(); }
    float inv = rsqrtf(red[0] * (1.0f / cD) + 1e-5f);
#pragma unroll
    for (int r = 0; r < 4; r++) {
        int c = t + 128 * r;
        out[(size_t)row * cD + c] = (lv[r] - mu) * inv * gg[c] + bb[c];
    }
}

// ------------------------- head ---------------------------------------------
__global__ void head_kernel(const float* __restrict__ Wm1, const float* __restrict__ bm1,
                            const float* __restrict__ Wm2, const float* __restrict__ bm2,
                            float* __restrict__ out) {
    int b = blockIdx.x, t = threadIdx.x;
    __shared__ float pooled[cD];
    float s = 0.f;
    for (int l = 0; l < cL; l++) s += g_h[(size_t)(b * cL + l) * cD + t];
    pooled[t] = s;
    __syncthreads();
    float r = bm1[t];
    for (int d = 0; d < cD; d++) r += pooled[d] * Wm1[(size_t)d * cM + t];
    r = fmaxf(r, 0.f);
    __shared__ float red[512];
    red[t] = r * Wm2[t];
    __syncthreads();
#pragma unroll
    for (int st = 256; st > 0; st >>= 1) { if (t < st) red[t] += red[t + st]; __syncthreads(); }
    if (t == 0) out[b] = red[0] + bm2[0];
}

// ===========================================================================
extern "C" void kernel_launch(void* const* d_in, const int* in_sizes, int n_in,
                              void* d_out, int out_size) {
    const int*   cell_types = (const int*)  d_in[0];
    const float* distances  = (const float*)d_in[1];
    const float* cell_emb   = (const float*)d_in[2];
    const float* Kqk = (const float*)d_in[3];
    const float* Kqr = (const float*)d_in[4];
    const float* Kkr = (const float*)d_in[5];
    const float* Vqk = (const float*)d_in[6];
    const float* Vqr = (const float*)d_in[7];
    const float* Vkr = (const float*)d_in[8];

    int iWq = 9, ibq, iWk, ibk, iWv, ibv, iWo, ibo;
    if (in_sizes[10] == cNL * cD) {
        ibq = 10; iWk = 11; ibk = 12; iWv = 13; ibv = 14; iWo = 15; ibo = 16;
    } else {
        iWk = 10; iWv = 11; iWo = 12; ibq = 13; ibk = 14; ibv = 15; ibo = 16;
    }
    const float* Wq = (const float*)d_in[iWq];
    const float* bq = (const float*)d_in[ibq];
    const float* Wk = (const float*)d_in[iWk];
    const float* bk = (const float*)d_in[ibk];
    const float* Wv = (const float*)d_in[iWv];
    const float* bv = (const float*)d_in[ibv];
    const float* Wo = (const float*)d_in[iWo];
    const float* bo = (const float*)d_in[ibo];
    const float* W1  = (const float*)d_in[17];
    const float* b1  = (const float*)d_in[18];
    const float* W2  = (const float*)d_in[19];
    const float* b2  = (const float*)d_in[20];
    const float* g1  = (const float*)d_in[21];
    const float* be1 = (const float*)d_in[22];
    const float* g2  = (const float*)d_in[23];
    const float* be2 = (const float*)d_in[24];
    const float* Wm1 = (const float*)d_in[25];
    const float* bm1 = (const float*)d_in[26];
    const float* Wm2 = (const float*)d_in[27];
    const float* bm2 = (const float*)d_in[28];
    float* out = (float*)d_out;

    float *p_h, *p_q, *p_k, *p_v, *p_z, *p_o, *p_h2, *p_f;
    cudaGetSymbolAddress((void**)&p_h,  g_h);
    cudaGetSymbolAddress((void**)&p_q,  g_q);
    cudaGetSymbolAddress((void**)&p_k,  g_k);
    cudaGetSymbolAddress((void**)&p_v,  g_v);
    cudaGetSymbolAddress((void**)&p_z,  g_z);
    cudaGetSymbolAddress((void**)&p_o,  g_o);
    cudaGetSymbolAddress((void**)&p_h2, g_h2);
    cudaGetSymbolAddress((void**)&p_f,  g_f);

    static const int FLASH_SMEM =
        (64 * SC_STRIDE) * 4 + 64 * 512 +
        (32 * 65 + 2112 + 64 * 16 + 64 * 16 + 16 * 256 + 256 + 256 + 64 + 448 + 16) * 4;
    cudaFuncSetAttribute(flash_attn_kernel,
                         cudaFuncAttributeMaxDynamicSharedMemorySize, FLASH_SMEM);
    cudaFuncSetAttribute(mma_gemm<false, true>,
                         cudaFuncAttributeMaxDynamicSharedMemorySize, GSM_BYTES);
    cudaFuncSetAttribute(mma_gemm<false, false>,
                         cudaFuncAttributeMaxDynamicSharedMemorySize, GSM_BYTES);
    cudaFuncSetAttribute(mma_gemm<true, false>,
                         cudaFuncAttributeMaxDynamicSharedMemorySize, GSM_BYTES);

    didx_kernel<<<(cB * cL * cL) / 256, 256>>>(distances);
    embed_kernel<<<cBL, 256>>>(cell_types, cell_emb);
    prep_kernel<<<1, 448>>>(Kkr, Vqk, Vqr, Vkr);

    dim3 gQKV(cD / 128, cBL / 128, 3);      // 192 CTAs
    dim3 gD  (cD / 128, cBL / 128);         // 64 CTAs
    dim3 gFF1(cFF / 128, cBL / 128);        // 256 CTAs
    dim3 gFlash(cL / 64, cB * cH);          // 512 CTAs

    for (int ly = 0; ly < cNL; ly++) {
        const float* wq  = Wq + (size_t)ly * cD * cD;
        const float* wk  = Wk + (size_t)ly * cD * cD;
        const float* wv  = Wv + (size_t)ly * cD * cD;
        const float* wo  = Wo + (size_t)ly * cD * cD;
        const float* bqp = bq + (size_t)ly * cD;
        const float* bkp = bk + (size_t)ly * cD;
        const float* bvp = bv + (size_t)ly * cD;
        const float* bop = bo + (size_t)ly * cD;
        const float* w1  = W1 + (size_t)ly * cD * cFF;
        const float* b1p = b1 + (size_t)ly * cFF;
        const float* w2  = W2 + (size_t)ly * cFF * cD;
        const float* b2p = b2 + (size_t)ly * cD;
        const float* g1p  = g1  + (size_t)ly * cD;
        const float* be1p = be1 + (size_t)ly * cD;
        const float* g2p  = g2  + (size_t)ly * cD;
        const float* be2p = be2 + (size_t)ly * cD;

        GArgs aQKV = { p_h, wq, wk, wv, bqp, bkp, bvp, p_q, p_k, p_v };
        mma_gemm<false, true><<<gQKV, 256, GSM_BYTES>>>(aQKV, cBL, cD, cD);

        qke_kernel<<<cBL, 256>>>(Kqk, Kqr);
        flash_attn_kernel<<<gFlash, 256, FLASH_SMEM>>>();

        GArgs aO = { p_z, wo, 0, 0, bop, 0, 0, p_o, 0, 0 };
        mma_gemm<false, false><<<gD, 256, GSM_BYTES>>>(aO, cBL, cD, cD);
        ln_kernel<<<cBL, 128>>>(p_h, p_o, g1p, be1p, p_h2);

        GArgs aF1 = { p_h2, w1, 0, 0, b1p, 0, 0, p_f, 0, 0 };
        mma_gemm<true, false><<<gFF1, 256, GSM_BYTES>>>(aF1, cBL, cFF, cD);

        GArgs aF2 = { p_f, w2, 0, 0, b2p, 0, 0, p_o, 0, 0 };
        mma_gemm<false, false><<<gD, 256, GSM_BYTES>>>(aF2, cBL, cD, cFF);

        ln_kernel<<<cBL, 128>>>(p_h2, p_o, g2p, be2p, p_h);
    }

    head_kernel<<<cB, 512>>>(Wm1, bm1, Wm2, bm2, out);
}

// round 7
// speedup vs baseline: 1.8197x; 1.8197x over previous
#include <cuda_runtime.h>
#include <math.h>
#include <stdint.h>

#define cB 4
#define cL 512
#define cD 512
#define cH 16
#define cKH 32
#define cFF 2048
#define cNL 8
#define cND 14
#define cM 512
#define cBL (cB*cL)
#define SCALEF 0.17677669529663687f  // 1/sqrt(32)

// ------------------------- scratch (static device globals) ------------------
__device__ float g_h [cBL*cD];
__device__ float g_q [cBL*cD];
__device__ float g_k [cBL*cD];
__device__ float g_v [cBL*cD];
__device__ float g_z [cBL*cD];
__device__ float g_o [cBL*cD];
__device__ float g_h2[cBL*cD];
__device__ float g_f [cBL*cFF];
__device__ float g_qE [cB*cH*cL*cND];
__device__ float g_kE [cB*cH*cL*cND];
__device__ unsigned char g_didx[cB*cL*cL];
__device__ float g_Vsum[cND*cKH];
__device__ float g_sumKkr[cND];

// ------------------------- helpers ------------------------------------------
__device__ __forceinline__ uint32_t smem_u32(const void* p) {
    uint32_t a;
    asm("{ .reg .u64 t; cvta.to.shared.u64 t, %1; cvt.u32.u64 %0, t; }" : "=r"(a) : "l"(p));
    return a;
}
__device__ __forceinline__ void cpasync16(uint32_t dst, const void* src) {
    asm volatile("cp.async.cg.shared.global [%0], [%1], 16;" :: "r"(dst), "l"(src));
}
#define CP_COMMIT() asm volatile("cp.async.commit_group;" ::: "memory")
#define CP_WAIT1()  asm volatile("cp.async.wait_group 1;" ::: "memory")

// split x into bf16 hi + bf16 lo (x ~= hi + lo), packed pairs for mma operands
__device__ __forceinline__ void split2(float x0, float x1, uint32_t& hi, uint32_t& lo) {
    uint32_t h;
    asm("cvt.rn.bf16x2.f32 %0, %1, %2;" : "=r"(h) : "f"(x1), "f"(x0));
    float h0 = __uint_as_float(h << 16);
    float h1 = __uint_as_float(h & 0xffff0000u);
    uint32_t l;
    asm("cvt.rn.bf16x2.f32 %0, %1, %2;" : "=r"(l) : "f"(x1 - h1), "f"(x0 - h0));
    hi = h; lo = l;
}
__device__ __forceinline__ void mma_bf16(float* c, const uint32_t* a, const uint32_t* b) {
    asm volatile(
        "mma.sync.aligned.m16n8k16.row.col.f32.bf16.bf16.f32 "
        "{%0,%1,%2,%3}, {%4,%5,%6,%7}, {%8,%9}, {%0,%1,%2,%3};\n"
        : "+f"(c[0]), "+f"(c[1]), "+f"(c[2]), "+f"(c[3])
        : "r"(a[0]), "r"(a[1]), "r"(a[2]), "r"(a[3]), "r"(b[0]), "r"(b[1]));
}

// ------------------------- bf16 3-term tensor-core GEMM ---------------------
// C[M,N] = A[M,K] @ W[K,N] + bias (opt exact GELU). CTA tile 128xBN, BK=16.
// 3-stage cp.async pipeline; raw fp32 tiles in smem; hi/lo split on load.
struct GArgs {
    const float* A;
    const float* W0; const float* W1; const float* W2;
    const float* c0; const float* c1; const float* c2;
    float* C0; float* C1; float* C2;
};

#define A_STRIDE 20
#define A_FLOATS (128 * A_STRIDE)

template<int BN, bool GELU, bool TRIPLE>
__global__ __launch_bounds__(256, 2) void mma_gemm(GArgs args, int Md, int Nd, int Kd) {
    constexpr int BSTR = BN + 4;
    constexpr int STAGE = A_FLOATS + 16 * BSTR;   // floats per stage
    constexpr int NT = BN / 16;                   // ntiles per warp (8 or 4)
    extern __shared__ float smem[];
    uint32_t smb = smem_u32(smem);

    int t = threadIdx.x;
    const float* A = args.A;
    const float* W; const float* bias; float* C;
    if (TRIPLE) {
        int z = blockIdx.z;
        W    = (z == 0) ? args.W0 : (z == 1) ? args.W1 : args.W2;
        bias = (z == 0) ? args.c0 : (z == 1) ? args.c1 : args.c2;
        C    = (z == 0) ? args.C0 : (z == 1) ? args.C1 : args.C2;
    } else { W = args.W0; bias = args.c0; C = args.C0; }

    int m0 = blockIdx.y * 128, n0 = blockIdx.x * BN;

    // cp.async issue for one chunk into stage s
    auto issue = [&](int ch, int s) {
        int k0 = ch << 4;
        uint32_t sa = smb + (uint32_t)(s * STAGE) * 4;
        uint32_t sb = sa + A_FLOATS * 4;
#pragma unroll
        for (int it = 0; it < 2; it++) {          // A: 128x16 = 512 float4-chunks
            int idx = t + it * 256;
            int row = idx >> 2, c4 = (idx & 3) << 2;
            cpasync16(sa + (uint32_t)(row * A_STRIDE + c4) * 4,
                      &A[(size_t)(m0 + row) * Kd + k0 + c4]);
        }
#pragma unroll
        for (int it = 0; it < BN / 64; it++) {    // B: 16xBN
            int idx = t + it * 256;
            int krow = idx / (BN / 4), c4 = (idx % (BN / 4)) << 2;
            cpasync16(sb + (uint32_t)(krow * BSTR + c4) * 4,
                      &W[(size_t)(k0 + krow) * Nd + n0 + c4]);
        }
    };

    int lane = t & 31, wid = t >> 5;
    int wm = wid & 3, wn = wid >> 2;
    int gr = lane >> 2, t4 = lane & 3;

    float c[2][NT][4];
#pragma unroll
    for (int i = 0; i < 2; i++)
#pragma unroll
        for (int j = 0; j < NT; j++)
#pragma unroll
            for (int q = 0; q < 4; q++) c[i][j][q] = 0.f;

    int nc = Kd >> 4;
    issue(0, 0); CP_COMMIT();
    issue(1, 1); CP_COMMIT();

    for (int ch = 0; ch < nc; ch++) {
        CP_WAIT1();
        __syncthreads();
        if (ch + 2 < nc) issue(ch + 2, (ch + 2) % 3);
        CP_COMMIT();

        const float* sA = smem + (ch % 3) * STAGE;
        const float* sB = sA + A_FLOATS;

        // A fragments (hi/lo)
        uint32_t ah[2][4], al[2][4];
#pragma unroll
        for (int i = 0; i < 2; i++) {
            int r0 = wm * 32 + i * 16 + gr;
            float2 p00 = *(const float2*)&sA[r0 * A_STRIDE + 2 * t4];
            float2 p10 = *(const float2*)&sA[(r0 + 8) * A_STRIDE + 2 * t4];
            float2 p01 = *(const float2*)&sA[r0 * A_STRIDE + 2 * t4 + 8];
            float2 p11 = *(const float2*)&sA[(r0 + 8) * A_STRIDE + 2 * t4 + 8];
            split2(p00.x, p00.y, ah[i][0], al[i][0]);
            split2(p10.x, p10.y, ah[i][1], al[i][1]);
            split2(p01.x, p01.y, ah[i][2], al[i][2]);
            split2(p11.x, p11.y, ah[i][3], al[i][3]);
        }
        // B fragments + MMAs
#pragma unroll
        for (int j = 0; j < NT; j++) {
            int n = wn * (BN / 2) + j * 8 + gr;
            float f0 = sB[(2 * t4) * BSTR + n];
            float f1 = sB[(2 * t4 + 1) * BSTR + n];
            float f2 = sB[(2 * t4 + 8) * BSTR + n];
            float f3 = sB[(2 * t4 + 9) * BSTR + n];
            uint32_t bh[2], bl[2];
            split2(f0, f1, bh[0], bl[0]);
            split2(f2, f3, bh[1], bl[1]);
#pragma unroll
            for (int i = 0; i < 2; i++) {
                mma_bf16(c[i][j], al[i], bh);
                mma_bf16(c[i][j], ah[i], bl);
                mma_bf16(c[i][j], ah[i], bh);
            }
        }
    }

    // --- epilogue ---
#pragma unroll
    for (int i = 0; i < 2; i++) {
        int rb = m0 + wm * 32 + i * 16 + gr;
#pragma unroll
        for (int j = 0; j < NT; j++) {
            int col = n0 + wn * (BN / 2) + j * 8 + t4 * 2;
            float2 bb = *(const float2*)&bias[col];
            float v0 = c[i][j][0] + bb.x, v1 = c[i][j][1] + bb.y;
            float v2 = c[i][j][2] + bb.x, v3 = c[i][j][3] + bb.y;
            if (GELU) {
                v0 = 0.5f * v0 * (1.0f + erff(v0 * 0.70710678118654752f));
                v1 = 0.5f * v1 * (1.0f + erff(v1 * 0.70710678118654752f));
                v2 = 0.5f * v2 * (1.0f + erff(v2 * 0.70710678118654752f));
                v3 = 0.5f * v3 * (1.0f + erff(v3 * 0.70710678118654752f));
            }
            *(float2*)&C[(size_t)rb * Nd + col] = make_float2(v0, v1);
            *(float2*)&C[(size_t)(rb + 8) * Nd + col] = make_float2(v2, v3);
        }
    }
}

// ------------------------- distance bucketize -------------------------------
__global__ void didx_kernel(const float* __restrict__ dist) {
    int i = blockIdx.x * blockDim.x + threadIdx.x;
    float d = dist[i];
    int idx = 0;
#pragma unroll
    for (int j = 1; j <= 14; j++) idx += (10.0f * (float)j < d) ? 1 : 0;
    if (idx > 13) idx = 13;
    g_didx[i] = (unsigned char)idx;
}

// ------------------------- embedding gather ---------------------------------
__global__ void embed_kernel(const int* __restrict__ ct, const float* __restrict__ emb) {
    int row = blockIdx.x;
    int c0  = ct[row];
    for (int c = threadIdx.x; c < cD; c += blockDim.x)
        g_h[(size_t)row * cD + c] = emb[(size_t)c0 * cD + c];
}

// ------------------------- tiny precompute ----------------------------------
__global__ void prep_kernel(const float* __restrict__ Kkr,
                            const float* __restrict__ Vqk,
                            const float* __restrict__ Vqr,
                            const float* __restrict__ Vkr) {
    int t = threadIdx.x;
    if (t < cND * cKH) g_Vsum[t] = Vqk[t] + Vqr[t] + Vkr[t];
    if (t < cND) {
        float s = 0.f;
        for (int k = 0; k < cKH; k++) s += Kkr[t * cKH + k];
        g_sumKkr[t] = s;
    }
}

// ------------------------- qE / kE ------------------------------------------
__global__ void qke_kernel(const float* __restrict__ Kqk, const float* __restrict__ Kqr) {
    __shared__ float sq[cD], sk[cD];
    __shared__ float sKa[cND * cKH], sKb[cND * cKH];
    int bl = blockIdx.x;
    int t  = threadIdx.x;
    for (int c = t; c < cD; c += 256) {
        sq[c] = g_q[(size_t)bl * cD + c];
        sk[c] = g_k[(size_t)bl * cD + c];
    }
    for (int c = t; c < cND * cKH; c += 256) { sKa[c] = Kqk[c]; sKb[c] = Kqr[c]; }
    __syncthreads();
    if (t < cH * cND) {
        int h = t / cND, d = t % cND;
        float s1 = 0.f, s2 = 0.f;
#pragma unroll
        for (int k = 0; k < cKH; k++) {
            s1 += sq[h * cKH + k] * sKa[d * cKH + k];
            s2 += sk[h * cKH + k] * sKb[d * cKH + k];
        }
        int b = bl / cL, l = bl % cL;
        size_t off = ((size_t)(b * cH + (size_t)h) * cL + l) * cND + d;
        g_qE[off] = s1;
        g_kE[off] = s2;
    }
}

// ------------------------- fused flash attention ----------------------------
#define SC_STRIDE 520
__global__ __launch_bounds__(256) void flash_attn_kernel() {
    extern __shared__ char smraw[];
    float* SC            = (float*)smraw;
    unsigned char* DIDX  = (unsigned char*)(SC + 64 * SC_STRIDE);
    float* QS   = (float*)(DIDX + 64 * 512);
    float* KS   = QS + 32 * 65;
    float* QES  = KS + 2112;
    float* KES  = QES + 64 * 16;
    float* HIST = KES + 64 * 16;
    float* REDM = HIST + 16 * 256;
    float* REDS = REDM + 256;
    float* RINV = REDS + 256;
    float* VSUM = RINV + 64;
    float* SKR  = VSUM + 448;

    int bh = blockIdx.y;
    int b  = bh >> 4, h = bh & 15;
    int l0 = blockIdx.x * 64;
    int t  = threadIdx.x;

#pragma unroll
    for (int r = 0; r < 8; r++) {
        int l = r * 8 + (t >> 5), k = t & 31;
        QS[k * 65 + l] = g_q[(size_t)(b * cL + l0 + l) * cD + h * 32 + k];
    }
    for (int idx = t; idx < 64 * cND; idx += 256) {
        int l = idx / cND, d = idx % cND;
        QES[l * 16 + d] = g_qE[((size_t)bh * cL + l0 + l) * cND + d];
    }
    {
        const int4* src = (const int4*)(g_didx + ((size_t)b * cL + l0) * cL);
        for (int idx = t; idx < 2048; idx += 256) ((int4*)DIDX)[idx] = src[idx];
    }
    for (int idx = t; idx < cND * 32; idx += 256) VSUM[idx] = g_Vsum[idx];
    if (t < cND) SKR[t] = g_sumKkr[t];
    __syncthreads();

    {
        int tx = t & 15, ty = t >> 4;
        for (int xt = 0; xt < 8; xt++) {
            int x0 = xt * 64;
#pragma unroll
            for (int r = 0; r < 8; r++) {
                int i = r * 8 + (t >> 5), k = t & 31;
                KS[k * 65 + i] = g_k[(size_t)(b * cL + x0 + i) * cD + h * 32 + k];
            }
            for (int idx = t; idx < 64 * cND; idx += 256) {
                int i2 = idx / cND, d = idx % cND;
                KES[i2 * 16 + d] = g_kE[((size_t)bh * cL + x0 + i2) * cND + d];
            }
            __syncthreads();
            float acc[4][4] = {};
#pragma unroll
            for (int k = 0; k < 32; k++) {
                float a[4], bb[4];
#pragma unroll
                for (int i = 0; i < 4; i++) a[i] = QS[k * 65 + ty + 16 * i];
#pragma unroll
                for (int j = 0; j < 4; j++) bb[j] = KS[k * 65 + tx + 16 * j];
#pragma unroll
                for (int i = 0; i < 4; i++)
#pragma unroll
                    for (int j = 0; j < 4; j++) acc[i][j] += a[i] * bb[j];
            }
#pragma unroll
            for (int i = 0; i < 4; i++)
#pragma unroll
                for (int j = 0; j < 4; j++) {
                    int li = ty + 16 * i, xj = tx + 16 * j;
                    int d = DIDX[li * 512 + x0 + xj];
                    SC[li * SC_STRIDE + x0 + xj] =
                        (acc[i][j] + QES[li * 16 + d] + KES[xj * 16 + d] + SKR[d]) * SCALEF;
                }
            __syncthreads();
        }
    }

    {
        int r = t >> 2, j = t & 3;
        float m = -1e30f;
        for (int i = 0; i < 128; i++) m = fmaxf(m, SC[r * SC_STRIDE + 4 * i + j]);
        REDM[t] = m;
        __syncthreads();
        m = fmaxf(fmaxf(REDM[r * 4], REDM[r * 4 + 1]), fmaxf(REDM[r * 4 + 2], REDM[r * 4 + 3]));
#pragma unroll
        for (int d = 0; d < 16; d++) HIST[d * 256 + t] = 0.f;
        float s = 0.f;
        for (int i = 0; i < 128; i++) {
            int x = 4 * i + j;
            float p = __expf(SC[r * SC_STRIDE + x] - m);
            SC[r * SC_STRIDE + x] = p;
            s += p;
            int d = DIDX[r * 512 + x];
            HIST[d * 256 + t] += p;
        }
        REDS[t] = s;
        __syncthreads();
        if (t < 64) RINV[t] = 1.0f / (REDS[4 * t] + REDS[4 * t + 1] + REDS[4 * t + 2] + REDS[4 * t + 3]);
        for (int idx = t; idx < 64 * cND; idx += 256) {
            int d = idx >> 6, r2 = idx & 63;
            QES[r2 * 16 + d] = HIST[d * 256 + 4 * r2]     + HIST[d * 256 + 4 * r2 + 1]
                             + HIST[d * 256 + 4 * r2 + 2] + HIST[d * 256 + 4 * r2 + 3];
        }
        __syncthreads();
    }

    {
        int txk = t & 31, tyr = t >> 5;
        float acc[8] = {};
        float* VS = KS;
        for (int xt = 0; xt < 8; xt++) {
            int x0 = xt * 64;
#pragma unroll
            for (int r = 0; r < 8; r++) {
                int i = r * 8 + tyr;
                VS[i * 33 + txk] = g_v[(size_t)(b * cL + x0 + i) * cD + h * 32 + txk];
            }
            __syncthreads();
#pragma unroll
            for (int xc = 0; xc < 16; xc++) {
                float4 a4[8];
#pragma unroll
                for (int i = 0; i < 8; i++)
                    a4[i] = *(const float4*)&SC[(i * 8 + tyr) * SC_STRIDE + x0 + xc * 4];
#pragma unroll
                for (int q = 0; q < 4; q++) {
                    float vb = VS[(xc * 4 + q) * 33 + txk];
                    const float* pa;
#pragma unroll
                    for (int i = 0; i < 8; i++) {
                        pa = &a4[i].x;
                        acc[i] += pa[q] * vb;
                    }
                }
            }
            __syncthreads();
        }
#pragma unroll
        for (int i = 0; i < 8; i++) {
            int l = i * 8 + tyr;
            float zv = acc[i];
#pragma unroll
            for (int d = 0; d < cND; d++) zv += QES[l * 16 + d] * VSUM[d * 32 + txk];
            g_z[(size_t)(b * cL + l0 + l) * cD + h * 32 + txk] = zv * RINV[l];
        }
    }
}

// ------------------------- layernorm of (X + R) -----------------------------
__global__ void ln_kernel(const float* __restrict__ X, const float* __restrict__ R,
                          const float* __restrict__ gg, const float* __restrict__ bb,
                          float* __restrict__ out) {
    int row = blockIdx.x, t = threadIdx.x;
    float lv[4];
    float s = 0.f;
#pragma unroll
    for (int r = 0; r < 4; r++) {
        int c = t + 128 * r;
        lv[r] = X[(size_t)row * cD + c] + R[(size_t)row * cD + c];
        s += lv[r];
    }
    __shared__ float red[128];
    red[t] = s; __syncthreads();
#pragma unroll
    for (int st = 64; st > 0; st >>= 1) { if (t < st) red[t] += red[t + st]; __syncthreads(); }
    float mu = red[0] * (1.0f / cD);
    __syncthreads();
    float vs = 0.f;
#pragma unroll
    for (int r = 0; r < 4; r++) { float d = lv[r] - mu; vs += d * d; }
    red[t] = vs; __syncthreads();
#pragma unroll
    for (int st = 64; st > 0; st >>= 1) { if (t < st) red[t] += red[t + st]; __syncthreads(); }
    float inv = rsqrtf(red[0] * (1.0f / cD) + 1e-5f);
#pragma unroll
    for (int r = 0; r < 4; r++) {
        int c = t + 128 * r;
        out[(size_t)row * cD + c] = (lv[r] - mu) * inv * gg[c] + bb[c];
    }
}

// ------------------------- head ---------------------------------------------
__global__ void head_kernel(const float* __restrict__ Wm1, const float* __restrict__ bm1,
                            const float* __restrict__ Wm2, const float* __restrict__ bm2,
                            float* __restrict__ out) {
    int b = blockIdx.x, t = threadIdx.x;
    __shared__ float pooled[cD];
    float s = 0.f;
    for (int l = 0; l < cL; l++) s += g_h[(size_t)(b * cL + l) * cD + t];
    pooled[t] = s;
    __syncthreads();
    float r = bm1[t];
    for (int d = 0; d < cD; d++) r += pooled[d] * Wm1[(size_t)d * cM + t];
    r = fmaxf(r, 0.f);
    __shared__ float red[512];
    red[t] = r * Wm2[t];
    __syncthreads();
#pragma unroll
    for (int st = 256; st > 0; st >>= 1) { if (t < st) red[t] += red[t + st]; __syncthreads(); }
    if (t == 0) out[b] = red[0] + bm2[0];
}

// ===========================================================================
extern "C" void kernel_launch(void* const* d_in, const int* in_sizes, int n_in,
                              void* d_out, int out_size) {
    const int*   cell_types = (const int*)  d_in[0];
    const float* distances  = (const float*)d_in[1];
    const float* cell_emb   = (const float*)d_in[2];
    const float* Kqk = (const float*)d_in[3];
    const float* Kqr = (const float*)d_in[4];
    const float* Kkr = (const float*)d_in[5];
    const float* Vqk = (const float*)d_in[6];
    const float* Vqr = (const float*)d_in[7];
    const float* Vkr = (const float*)d_in[8];

    int iWq = 9, ibq, iWk, ibk, iWv, ibv, iWo, ibo;
    if (in_sizes[10] == cNL * cD) {
        ibq = 10; iWk = 11; ibk = 12; iWv = 13; ibv = 14; iWo = 15; ibo = 16;
    } else {
        iWk = 10; iWv = 11; iWo = 12; ibq = 13; ibk = 14; ibv = 15; ibo = 16;
    }
    const float* Wq = (const float*)d_in[iWq];
    const float* bq = (const float*)d_in[ibq];
    const float* Wk = (const float*)d_in[iWk];
    const float* bk = (const float*)d_in[ibk];
    const float* Wv = (const float*)d_in[iWv];
    const float* bv = (const float*)d_in[ibv];
    const float* Wo = (const float*)d_in[iWo];
    const float* bo = (const float*)d_in[ibo];
    const float* W1  = (const float*)d_in[17];
    const float* b1  = (const float*)d_in[18];
    const float* W2  = (const float*)d_in[19];
    const float* b2  = (const float*)d_in[20];
    const float* g1  = (const float*)d_in[21];
    const float* be1 = (const float*)d_in[22];
    const float* g2  = (const float*)d_in[23];
    const float* be2 = (const float*)d_in[24];
    const float* Wm1 = (const float*)d_in[25];
    const float* bm1 = (const float*)d_in[26];
    const float* Wm2 = (const float*)d_in[27];
    const float* bm2 = (const float*)d_in[28];
    float* out = (float*)d_out;

    float *p_h, *p_q, *p_k, *p_v, *p_z, *p_o, *p_h2, *p_f;
    cudaGetSymbolAddress((void**)&p_h,  g_h);
    cudaGetSymbolAddress((void**)&p_q,  g_q);
    cudaGetSymbolAddress((void**)&p_k,  g_k);
    cudaGetSymbolAddress((void**)&p_v,  g_v);
    cudaGetSymbolAddress((void**)&p_z,  g_z);
    cudaGetSymbolAddress((void**)&p_o,  g_o);
    cudaGetSymbolAddress((void**)&p_h2, g_h2);
    cudaGetSymbolAddress((void**)&p_f,  g_f);

    static const int FLASH_SMEM =
        (64 * SC_STRIDE) * 4 + 64 * 512 +
        (32 * 65 + 2112 + 64 * 16 + 64 * 16 + 16 * 256 + 256 + 256 + 64 + 448 + 16) * 4;
    cudaFuncSetAttribute(flash_attn_kernel,
                         cudaFuncAttributeMaxDynamicSharedMemorySize, FLASH_SMEM);

    const int SM128 = 3 * (A_FLOATS + 16 * 132) * 4;   // BN=128 stages
    const int SM64  = 3 * (A_FLOATS + 16 * 68) * 4;    // BN=64 stages
    cudaFuncSetAttribute(mma_gemm<128, false, true>,
                         cudaFuncAttributeMaxDynamicSharedMemorySize, SM128);
    cudaFuncSetAttribute(mma_gemm<128, true, false>,
                         cudaFuncAttributeMaxDynamicSharedMemorySize, SM128);
    cudaFuncSetAttribute(mma_gemm<64, false, false>,
                         cudaFuncAttributeMaxDynamicSharedMemorySize, SM64);

    didx_kernel<<<(cB * cL * cL) / 256, 256>>>(distances);
    embed_kernel<<<cBL, 256>>>(cell_types, cell_emb);
    prep_kernel<<<1, 448>>>(Kkr, Vqk, Vqr, Vkr);

    dim3 gQKV(cD / 128, cBL / 128, 3);      // 192 CTAs
    dim3 gN64(cD / 64, cBL / 128);          // 128 CTAs (O-proj, FF2)
    dim3 gFF1(cFF / 128, cBL / 128);        // 256 CTAs
    dim3 gFlash(cL / 64, cB * cH);          // 512 CTAs

    for (int ly = 0; ly < cNL; ly++) {
        const float* wq  = Wq + (size_t)ly * cD * cD;
        const float* wk  = Wk + (size_t)ly * cD * cD;
        const float* wv  = Wv + (size_t)ly * cD * cD;
        const float* wo  = Wo + (size_t)ly * cD * cD;
        const float* bqp = bq + (size_t)ly * cD;
        const float* bkp = bk + (size_t)ly * cD;
        const float* bvp = bv + (size_t)ly * cD;
        const float* bop = bo + (size_t)ly * cD;
        const float* w1  = W1 + (size_t)ly * cD * cFF;
        const float* b1p = b1 + (size_t)ly * cFF;
        const float* w2  = W2 + (size_t)ly * cFF * cD;
        const float* b2p = b2 + (size_t)ly * cD;
        const float* g1p  = g1  + (size_t)ly * cD;
        const float* be1p = be1 + (size_t)ly * cD;
        const float* g2p  = g2  + (size_t)ly * cD;
        const float* be2p = be2 + (size_t)ly * cD;

        GArgs aQKV = { p_h, wq, wk, wv, bqp, bkp, bvp, p_q, p_k, p_v };
        mma_gemm<128, false, true><<<gQKV, 256, SM128>>>(aQKV, cBL, cD, cD);

        qke_kernel<<<cBL, 256>>>(Kqk, Kqr);
        flash_attn_kernel<<<gFlash, 256, FLASH_SMEM>>>();

        GArgs aO = { p_z, wo, 0, 0, bop, 0, 0, p_o, 0, 0 };
        mma_gemm<64, false, false><<<gN64, 256, SM64>>>(aO, cBL, cD, cD);
        ln_kernel<<<cBL, 128>>>(p_h, p_o, g1p, be1p, p_h2);

        GArgs aF1 = { p_h2, w1, 0, 0, b1p, 0, 0, p_f, 0, 0 };
        mma_gemm<128, true, false><<<gFF1, 256, SM128>>>(aF1, cBL, cFF, cD);

        GArgs aF2 = { p_f, w2, 0, 0, b2p, 0, 0, p_o, 0, 0 };
        mma_gemm<64, false, false><<<gN64, 256, SM64>>>(aF2, cBL, cD, cFF);

        ln_kernel<<<cBL, 128>>>(p_h2, p_o, g2p, be2p, p_h);
    }

    head_kernel<<<cB, 512>>>(Wm1, bm1, Wm2, bm2, out);
}

// round 8
// speedup vs baseline: 2.0308x; 1.1160x over previous
#include <cuda_runtime.h>
#include <math.h>
#include <stdint.h>

#define cB 4
#define cL 512
#define cD 512
#define cH 16
#define cKH 32
#define cFF 2048
#define cNL 8
#define cND 14
#define cM 512
#define cBL (cB*cL)
#define SCALEF 0.17677669529663687f  // 1/sqrt(32)

// ------------------------- scratch (static device globals) ------------------
__device__ float g_h [cBL*cD];
__device__ float g_q [cBL*cD];
__device__ float g_k [cBL*cD];
__device__ float g_v [cBL*cD];
__device__ float g_z [cBL*cD];
__device__ float g_o [cBL*cD];
__device__ float g_o2[cBL*cD];
__device__ float g_h2[cBL*cD];
__device__ float g_f [cBL*cFF];
__device__ float g_qE [cB*cH*cL*cND];
__device__ float g_kE [cB*cH*cL*cND];
__device__ unsigned char g_didx[cB*cL*cL];
__device__ float g_Vsum[cND*cKH];
__device__ float g_sumKkr[cND];
__device__ float g_zb[cD];          // zero bias (never written)

// ------------------------- helpers ------------------------------------------
__device__ __forceinline__ uint32_t smem_u32(const void* p) {
    uint32_t a;
    asm("{ .reg .u64 t; cvta.to.shared.u64 t, %1; cvt.u32.u64 %0, t; }" : "=r"(a) : "l"(p));
    return a;
}
__device__ __forceinline__ void cpasync16(uint32_t dst, const void* src) {
    asm volatile("cp.async.cg.shared.global [%0], [%1], 16;" :: "r"(dst), "l"(src));
}
#define CP_COMMIT() asm volatile("cp.async.commit_group;" ::: "memory")
#define CP_WAIT1()  asm volatile("cp.async.wait_group 1;" ::: "memory")

// split (x0,x1) into packed bf16x2 hi + lo, low half = x0
__device__ __forceinline__ void split2(float x0, float x1, uint32_t& hi, uint32_t& lo) {
    uint32_t h;
    asm("cvt.rn.bf16x2.f32 %0, %1, %2;" : "=r"(h) : "f"(x1), "f"(x0));
    float h0 = __uint_as_float(h << 16);
    float h1 = __uint_as_float(h & 0xffff0000u);
    uint32_t l;
    asm("cvt.rn.bf16x2.f32 %0, %1, %2;" : "=r"(l) : "f"(x1 - h1), "f"(x0 - h0));
    hi = h; lo = l;
}
__device__ __forceinline__ void mma_bf16(float* c, const uint32_t* a, const uint32_t* b) {
    asm volatile(
        "mma.sync.aligned.m16n8k16.row.col.f32.bf16.bf16.f32 "
        "{%0,%1,%2,%3}, {%4,%5,%6,%7}, {%8,%9}, {%0,%1,%2,%3};\n"
        : "+f"(c[0]), "+f"(c[1]), "+f"(c[2]), "+f"(c[3])
        : "r"(a[0]), "r"(a[1]), "r"(a[2]), "r"(a[3]), "r"(b[0]), "r"(b[1]));
}

// ------------------------- bf16 3-term tensor-core GEMM ---------------------
struct GArgs {
    const float* A;
    const float* W0; const float* W1; const float* W2;
    const float* c0; const float* c1; const float* c2;
    float* C0; float* C1; float* C2;
};

#define A_STRIDE 20
#define A_FLOATS (128 * A_STRIDE)

template<int BN, bool GELU, bool TRIPLE>
__global__ __launch_bounds__(256, 2) void mma_gemm(GArgs args, int Md, int Nd, int Kd,
                                                   int ldA, int aStep) {
    constexpr int BSTR = BN + 4;
    constexpr int STAGE = A_FLOATS + 16 * BSTR;
    constexpr int NT = BN / 16;
    extern __shared__ float smem[];
    uint32_t smb = smem_u32(smem);

    int t = threadIdx.x;
    const float* A = args.A;
    const float* W; const float* bias; float* C;
    if (TRIPLE) {
        int z = blockIdx.z;
        A   += (size_t)z * aStep;
        W    = (z == 0) ? args.W0 : (z == 1) ? args.W1 : args.W2;
        bias = (z == 0) ? args.c0 : (z == 1) ? args.c1 : args.c2;
        C    = (z == 0) ? args.C0 : (z == 1) ? args.C1 : args.C2;
    } else { W = args.W0; bias = args.c0; C = args.C0; }

    int m0 = blockIdx.y * 128, n0 = blockIdx.x * BN;

    auto issue = [&](int ch, int s) {
        int k0 = ch << 4;
        uint32_t sa = smb + (uint32_t)(s * STAGE) * 4;
        uint32_t sb = sa + A_FLOATS * 4;
#pragma unroll
        for (int it = 0; it < 2; it++) {
            int idx = t + it * 256;
            int row = idx >> 2, c4 = (idx & 3) << 2;
            cpasync16(sa + (uint32_t)(row * A_STRIDE + c4) * 4,
                      &A[(size_t)(m0 + row) * ldA + k0 + c4]);
        }
#pragma unroll
        for (int it = 0; it < BN / 64; it++) {
            int idx = t + it * 256;
            int krow = idx / (BN / 4), c4 = (idx % (BN / 4)) << 2;
            cpasync16(sb + (uint32_t)(krow * BSTR + c4) * 4,
                      &W[(size_t)(k0 + krow) * Nd + n0 + c4]);
        }
    };

    int lane = t & 31, wid = t >> 5;
    int wm = wid & 3, wn = wid >> 2;
    int gr = lane >> 2, t4 = lane & 3;

    float c[2][NT][4];
#pragma unroll
    for (int i = 0; i < 2; i++)
#pragma unroll
        for (int j = 0; j < NT; j++)
#pragma unroll
            for (int q = 0; q < 4; q++) c[i][j][q] = 0.f;

    int nc = Kd >> 4;
    issue(0, 0); CP_COMMIT();
    issue(1, 1); CP_COMMIT();

    for (int ch = 0; ch < nc; ch++) {
        CP_WAIT1();
        __syncthreads();
        if (ch + 2 < nc) issue(ch + 2, (ch + 2) % 3);
        CP_COMMIT();

        const float* sA = smem + (ch % 3) * STAGE;
        const float* sB = sA + A_FLOATS;

        uint32_t ah[2][4], al[2][4];
#pragma unroll
        for (int i = 0; i < 2; i++) {
            int r0 = wm * 32 + i * 16 + gr;
            float2 p00 = *(const float2*)&sA[r0 * A_STRIDE + 2 * t4];
            float2 p10 = *(const float2*)&sA[(r0 + 8) * A_STRIDE + 2 * t4];
            float2 p01 = *(const float2*)&sA[r0 * A_STRIDE + 2 * t4 + 8];
            float2 p11 = *(const float2*)&sA[(r0 + 8) * A_STRIDE + 2 * t4 + 8];
            split2(p00.x, p00.y, ah[i][0], al[i][0]);
            split2(p10.x, p10.y, ah[i][1], al[i][1]);
            split2(p01.x, p01.y, ah[i][2], al[i][2]);
            split2(p11.x, p11.y, ah[i][3], al[i][3]);
        }
#pragma unroll
        for (int j = 0; j < NT; j++) {
            int n = wn * (BN / 2) + j * 8 + gr;
            float f0 = sB[(2 * t4) * BSTR + n];
            float f1 = sB[(2 * t4 + 1) * BSTR + n];
            float f2 = sB[(2 * t4 + 8) * BSTR + n];
            float f3 = sB[(2 * t4 + 9) * BSTR + n];
            uint32_t bh[2], bl[2];
            split2(f0, f1, bh[0], bl[0]);
            split2(f2, f3, bh[1], bl[1]);
#pragma unroll
            for (int i = 0; i < 2; i++) {
                mma_bf16(c[i][j], al[i], bh);
                mma_bf16(c[i][j], ah[i], bl);
                mma_bf16(c[i][j], ah[i], bh);
            }
        }
    }

#pragma unroll
    for (int i = 0; i < 2; i++) {
        int rb = m0 + wm * 32 + i * 16 + gr;
#pragma unroll
        for (int j = 0; j < NT; j++) {
            int col = n0 + wn * (BN / 2) + j * 8 + t4 * 2;
            float2 bb = *(const float2*)&bias[col];
            float v0 = c[i][j][0] + bb.x, v1 = c[i][j][1] + bb.y;
            float v2 = c[i][j][2] + bb.x, v3 = c[i][j][3] + bb.y;
            if (GELU) {
                v0 = 0.5f * v0 * (1.0f + erff(v0 * 0.70710678118654752f));
                v1 = 0.5f * v1 * (1.0f + erff(v1 * 0.70710678118654752f));
                v2 = 0.5f * v2 * (1.0f + erff(v2 * 0.70710678118654752f));
                v3 = 0.5f * v3 * (1.0f + erff(v3 * 0.70710678118654752f));
            }
            *(float2*)&C[(size_t)rb * Nd + col] = make_float2(v0, v1);
            *(float2*)&C[(size_t)(rb + 8) * Nd + col] = make_float2(v2, v3);
        }
    }
}

// ------------------------- distance bucketize -------------------------------
__global__ void didx_kernel(const float* __restrict__ dist) {
    int i = blockIdx.x * blockDim.x + threadIdx.x;
    float d = dist[i];
    int idx = 0;
#pragma unroll
    for (int j = 1; j <= 14; j++) idx += (10.0f * (float)j < d) ? 1 : 0;
    if (idx > 13) idx = 13;
    g_didx[i] = (unsigned char)idx;
}

// ------------------------- embedding gather ---------------------------------
__global__ void embed_kernel(const int* __restrict__ ct, const float* __restrict__ emb) {
    int row = blockIdx.x;
    int c0  = ct[row];
    for (int c = threadIdx.x; c < cD; c += blockDim.x)
        g_h[(size_t)row * cD + c] = emb[(size_t)c0 * cD + c];
}

// ------------------------- tiny precompute ----------------------------------
__global__ void prep_kernel(const float* __restrict__ Kkr,
                            const float* __restrict__ Vqk,
                            const float* __restrict__ Vqr,
                            const float* __restrict__ Vkr) {
    int t = threadIdx.x;
    if (t < cND * cKH) g_Vsum[t] = Vqk[t] + Vqr[t] + Vkr[t];
    if (t < cND) {
        float s = 0.f;
        for (int k = 0; k < cKH; k++) s += Kkr[t * cKH + k];
        g_sumKkr[t] = s;
    }
}

// ------------------------- qE / kE ------------------------------------------
__global__ void qke_kernel(const float* __restrict__ Kqk, const float* __restrict__ Kqr) {
    __shared__ float sq[cD], sk[cD];
    __shared__ float sKa[cND * cKH], sKb[cND * cKH];
    int bl = blockIdx.x;
    int t  = threadIdx.x;
    for (int c = t; c < cD; c += 256) {
        sq[c] = g_q[(size_t)bl * cD + c];
        sk[c] = g_k[(size_t)bl * cD + c];
    }
    for (int c = t; c < cND * cKH; c += 256) { sKa[c] = Kqk[c]; sKb[c] = Kqr[c]; }
    __syncthreads();
    if (t < cH * cND) {
        int h = t / cND, d = t % cND;
        float s1 = 0.f, s2 = 0.f;
#pragma unroll
        for (int k = 0; k < cKH; k++) {
            s1 += sq[h * cKH + k] * sKa[d * cKH + k];
            s2 += sk[h * cKH + k] * sKb[d * cKH + k];
        }
        int b = bl / cL, l = bl % cL;
        size_t off = ((size_t)(b * cH + (size_t)h) * cL + l) * cND + d;
        g_qE[off] = s1;
        g_kE[off] = s2;
    }
}

// ------------------------- fused flash attention (bf16 3-term MMA) ----------
#define SC_STRIDE 520
__global__ __launch_bounds__(256) void flash_attn_kernel() {
    extern __shared__ char smraw[];
    float* SC            = (float*)smraw;                         // 64*520
    unsigned char* DIDX  = (unsigned char*)(SC + 64 * SC_STRIDE); // 64*512 B
    float* QS   = (float*)(DIDX + 64 * 512);  // 64*33
    float* KS   = QS + 2112;                  // 64*33 (reused as VS in phase 3)
    float* QES  = KS + 2112;                  // 1024
    float* KES  = QES + 1024;                 // 1024
    float* HIST = KES + 1024;                 // 4096
    float* RMAX = HIST + 4096;                // 128
    float* REDS = RMAX + 128;                 // 256
    float* RINV = REDS + 256;                 // 64
    float* VSUM = RINV + 64;                  // 448
    float* SKR  = VSUM + 448;                 // 16

    int bh = blockIdx.y;
    int b  = bh >> 4, h = bh & 15;
    int l0 = blockIdx.x * 64;
    int t  = threadIdx.x;
    int lane = t & 31, wid = t >> 5;
    int wm = wid & 3, wn = wid >> 2;
    int gr = lane >> 2, t4 = lane & 3;

    // ---- preload Q (row-major), qE, didx strip, Vsum, sumKkr ----
#pragma unroll
    for (int r = 0; r < 8; r++) {
        int l = r * 8 + (t >> 5), k = t & 31;
        QS[l * 33 + k] = g_q[(size_t)(b * cL + l0 + l) * cD + h * 32 + k];
    }
    for (int idx = t; idx < 64 * cND; idx += 256) {
        int l = idx / cND, d = idx % cND;
        QES[l * 16 + d] = g_qE[((size_t)bh * cL + l0 + l) * cND + d];
    }
    {
        const int4* src = (const int4*)(g_didx + ((size_t)b * cL + l0) * cL);
        for (int idx = t; idx < 2048; idx += 256) ((int4*)DIDX)[idx] = src[idx];
    }
    for (int idx = t; idx < cND * 32; idx += 256) VSUM[idx] = g_Vsum[idx];
    if (t < cND) SKR[t] = g_sumKkr[t];
    __syncthreads();

    // ---- Q fragments (hoisted) ----
    uint32_t qh[2][4], ql[2][4];
    {
        int r0 = wm * 16 + gr;
#pragma unroll
        for (int ks = 0; ks < 2; ks++) {
            int k0 = ks * 16 + 2 * t4;
            split2(QS[r0 * 33 + k0],       QS[r0 * 33 + k0 + 1],       qh[ks][0], ql[ks][0]);
            split2(QS[(r0 + 8) * 33 + k0], QS[(r0 + 8) * 33 + k0 + 1], qh[ks][1], ql[ks][1]);
            split2(QS[r0 * 33 + k0 + 8],   QS[r0 * 33 + k0 + 9],       qh[ks][2], ql[ks][2]);
            split2(QS[(r0 + 8) * 33 + k0 + 8], QS[(r0 + 8) * 33 + k0 + 9], qh[ks][3], ql[ks][3]);
        }
    }
    float mx0 = -1e30f, mx1 = -1e30f;

    // ---- phase 1: scores via MMA, bias epilogue, fused row-max ----
    for (int xt = 0; xt < 8; xt++) {
        int x0 = xt * 64;
#pragma unroll
        for (int r = 0; r < 8; r++) {
            int i = r * 8 + (t >> 5), k = t & 31;
            KS[i * 33 + k] = g_k[(size_t)(b * cL + x0 + i) * cD + h * 32 + k];
        }
        for (int idx = t; idx < 64 * cND; idx += 256) {
            int i2 = idx / cND, d = idx % cND;
            KES[i2 * 16 + d] = g_kE[((size_t)bh * cL + x0 + i2) * cND + d];
        }
        __syncthreads();

        float acc[4][4] = {};
#pragma unroll
        for (int jn = 0; jn < 4; jn++) {
            int c0 = wn * 32 + jn * 8 + gr;
#pragma unroll
            for (int ks = 0; ks < 2; ks++) {
                int k0 = ks * 16 + 2 * t4;
                uint32_t kb[2], kl[2];
                split2(KS[c0 * 33 + k0],     KS[c0 * 33 + k0 + 1], kb[0], kl[0]);
                split2(KS[c0 * 33 + k0 + 8], KS[c0 * 33 + k0 + 9], kb[1], kl[1]);
                mma_bf16(acc[jn], ql[ks], kb);
                mma_bf16(acc[jn], qh[ks], kl);
                mma_bf16(acc[jn], qh[ks], kb);
            }
        }
        int r0 = wm * 16 + gr;
#pragma unroll
        for (int jn = 0; jn < 4; jn++) {
            int cbase = wn * 32 + jn * 8 + 2 * t4;
#pragma unroll
            for (int q = 0; q < 4; q++) {
                int row = (q & 2) ? r0 + 8 : r0;
                int ct  = cbase + (q & 1);
                int col = x0 + ct;
                int d = DIDX[row * 512 + col];
                float e = (acc[jn][q] + QES[row * 16 + d] + KES[ct * 16 + d] + SKR[d]) * SCALEF;
                SC[row * SC_STRIDE + col] = e;
                if (q & 2) mx1 = fmaxf(mx1, e); else mx0 = fmaxf(mx0, e);
            }
        }
        __syncthreads();
    }
    mx0 = fmaxf(mx0, __shfl_xor_sync(0xffffffffu, mx0, 1));
    mx0 = fmaxf(mx0, __shfl_xor_sync(0xffffffffu, mx0, 2));
    mx1 = fmaxf(mx1, __shfl_xor_sync(0xffffffffu, mx1, 1));
    mx1 = fmaxf(mx1, __shfl_xor_sync(0xffffffffu, mx1, 2));
    if (t4 == 0) {
        RMAX[(wm * 16 + gr) + 64 * wn]     = mx0;
        RMAX[(wm * 16 + gr + 8) + 64 * wn] = mx1;
    }
    __syncthreads();

    // ---- phase 2: exp + row-sum + bucket histogram ----
    {
        int r = t >> 2, j = t & 3;
        float m = fmaxf(RMAX[r], RMAX[r + 64]);
#pragma unroll
        for (int d = 0; d < 16; d++) HIST[d * 256 + t] = 0.f;
        float s = 0.f;
        for (int i = 0; i < 128; i++) {
            int x = 4 * i + j;
            float p = __expf(SC[r * SC_STRIDE + x] - m);
            SC[r * SC_STRIDE + x] = p;
            s += p;
            int d = DIDX[r * 512 + x];
            HIST[d * 256 + t] += p;
        }
        REDS[t] = s;
        __syncthreads();
        if (t < 64) RINV[t] = 1.0f / (REDS[4 * t] + REDS[4 * t + 1] + REDS[4 * t + 2] + REDS[4 * t + 3]);
        for (int idx = t; idx < 64 * cND; idx += 256) {
            int d = idx >> 6, r2 = idx & 63;
            QES[r2 * 16 + d] = HIST[d * 256 + 4 * r2]     + HIST[d * 256 + 4 * r2 + 1]
                             + HIST[d * 256 + 4 * r2 + 2] + HIST[d * 256 + 4 * r2 + 3];
        }
        __syncthreads();
    }

    // ---- phase 3: z = P@V (MMA) + hist@Vsum, normalized ----
    {
        float zc[2][4] = {};
        float* VS = KS;
        for (int xt = 0; xt < 8; xt++) {
            int x0 = xt * 64;
#pragma unroll
            for (int r = 0; r < 8; r++) {
                int i = r * 8 + (t >> 5), k = t & 31;
                VS[i * 33 + k] = g_v[(size_t)(b * cL + x0 + i) * cD + h * 32 + k];
            }
            __syncthreads();
            int r0 = wm * 16 + gr;
#pragma unroll
            for (int ks = 0; ks < 4; ks++) {
                int kk = x0 + ks * 16 + 2 * t4;
                uint32_t pah[4], pal[4];
                split2(SC[r0 * SC_STRIDE + kk],           SC[r0 * SC_STRIDE + kk + 1],           pah[0], pal[0]);
                split2(SC[(r0 + 8) * SC_STRIDE + kk],     SC[(r0 + 8) * SC_STRIDE + kk + 1],     pah[1], pal[1]);
                split2(SC[r0 * SC_STRIDE + kk + 8],       SC[r0 * SC_STRIDE + kk + 9],           pah[2], pal[2]);
                split2(SC[(r0 + 8) * SC_STRIDE + kk + 8], SC[(r0 + 8) * SC_STRIDE + kk + 9],     pah[3], pal[3]);
                int kv = ks * 16 + 2 * t4;
#pragma unroll
                for (int jn = 0; jn < 2; jn++) {
                    int col = wn * 16 + jn * 8 + gr;
                    uint32_t vh[2], vl[2];
                    split2(VS[kv * 33 + col],       VS[(kv + 1) * 33 + col], vh[0], vl[0]);
                    split2(VS[(kv + 8) * 33 + col], VS[(kv + 9) * 33 + col], vh[1], vl[1]);
                    mma_bf16(zc[jn], pal, vh);
                    mma_bf16(zc[jn], pah, vl);
                    mma_bf16(zc[jn], pah, vh);
                }
            }
            __syncthreads();
        }
        int r0 = wm * 16 + gr;
#pragma unroll
        for (int jn = 0; jn < 2; jn++) {
            int col0 = wn * 16 + jn * 8 + 2 * t4;
#pragma unroll
            for (int qq = 0; qq < 2; qq++) {
                int row = r0 + qq * 8;
                float z0 = zc[jn][qq * 2 + 0], z1 = zc[jn][qq * 2 + 1];
#pragma unroll
                for (int d = 0; d < cND; d++) {
                    float hv = QES[row * 16 + d];
                    z0 += hv * VSUM[d * 32 + col0];
                    z1 += hv * VSUM[d * 32 + col0 + 1];
                }
                float ri = RINV[row];
                *(float2*)&g_z[(size_t)(b * cL + l0 + row) * cD + h * 32 + col0] =
                    make_float2(z0 * ri, z1 * ri);
            }
        }
    }
}

// ------------------------- layernorm of (X + R1 + R2) -----------------------
__global__ void ln3_kernel(const float* __restrict__ X, const float* __restrict__ R1,
                           const float* __restrict__ R2,
                           const float* __restrict__ gg, const float* __restrict__ bb,
                           float* __restrict__ out) {
    int row = blockIdx.x, t = threadIdx.x;
    float lv[4];
    float s = 0.f;
#pragma unroll
    for (int r = 0; r < 4; r++) {
        int c = t + 128 * r;
        lv[r] = X[(size_t)row * cD + c] + R1[(size_t)row * cD + c] + R2[(size_t)row * cD + c];
        s += lv[r];
    }
    __shared__ float red[128];
    red[t] = s; __syncthreads();
#pragma unroll
    for (int st = 64; st > 0; st >>= 1) { if (t < st) red[t] += red[t + st]; __syncthreads(); }
    float mu = red[0] * (1.0f / cD);
    __syncthreads();
    float vs = 0.f;
#pragma unroll
    for (int r = 0; r < 4; r++) { float d = lv[r] - mu; vs += d * d; }
    red[t] = vs; __syncthreads();
#pragma unroll
    for (int st = 64; st > 0; st >>= 1) { if (t < st) red[t] += red[t + st]; __syncthreads(); }
    float inv = rsqrtf(red[0] * (1.0f / cD) + 1e-5f);
#pragma unroll
    for (int r = 0; r < 4; r++) {
        int c = t + 128 * r;
        out[(size_t)row * cD + c] = (lv[r] - mu) * inv * gg[c] + bb[c];
    }
}

// ------------------------- head ---------------------------------------------
__global__ void head_kernel(const float* __restrict__ Wm1, const float* __restrict__ bm1,
                            const float* __restrict__ Wm2, const float* __restrict__ bm2,
                            float* __restrict__ out) {
    int b = blockIdx.x, t = threadIdx.x;
    __shared__ float pooled[cD];
    float s = 0.f;
    for (int l = 0; l < cL; l++) s += g_h[(size_t)(b * cL + l) * cD + t];
    pooled[t] = s;
    __syncthreads();
    float r = bm1[t];
    for (int d = 0; d < cD; d++) r += pooled[d] * Wm1[(size_t)d * cM + t];
    r = fmaxf(r, 0.f);
    __shared__ float red[512];
    red[t] = r * Wm2[t];
    __syncthreads();
#pragma unroll
    for (int st = 256; st > 0; st >>= 1) { if (t < st) red[t] += red[t + st]; __syncthreads(); }
    if (t == 0) out[b] = red[0] + bm2[0];
}

// ===========================================================================
extern "C" void kernel_launch(void* const* d_in, const int* in_sizes, int n_in,
                              void* d_out, int out_size) {
    const int*   cell_types = (const int*)  d_in[0];
    const float* distances  = (const float*)d_in[1];
    const float* cell_emb   = (const float*)d_in[2];
    const float* Kqk = (const float*)d_in[3];
    const float* Kqr = (const float*)d_in[4];
    const float* Kkr = (const float*)d_in[5];
    const float* Vqk = (const float*)d_in[6];
    const float* Vqr = (const float*)d_in[7];
    const float* Vkr = (const float*)d_in[8];

    int iWq = 9, ibq, iWk, ibk, iWv, ibv, iWo, ibo;
    if (in_sizes[10] == cNL * cD) {
        ibq = 10; iWk = 11; ibk = 12; iWv = 13; ibv = 14; iWo = 15; ibo = 16;
    } else {
        iWk = 10; iWv = 11; iWo = 12; ibq = 13; ibk = 14; ibv = 15; ibo = 16;
    }
    const float* Wq = (const float*)d_in[iWq];
    const float* bq = (const float*)d_in[ibq];
    const float* Wk = (const float*)d_in[iWk];
    const float* bk = (const float*)d_in[ibk];
    const float* Wv = (const float*)d_in[iWv];
    const float* bv = (const float*)d_in[ibv];
    const float* Wo = (const float*)d_in[iWo];
    const float* bo = (const float*)d_in[ibo];
    const float* W1  = (const float*)d_in[17];
    const float* b1  = (const float*)d_in[18];
    const float* W2  = (const float*)d_in[19];
    const float* b2  = (const float*)d_in[20];
    const float* g1  = (const float*)d_in[21];
    const float* be1 = (const float*)d_in[22];
    const float* g2  = (const float*)d_in[23];
    const float* be2 = (const float*)d_in[24];
    const float* Wm1 = (const float*)d_in[25];
    const float* bm1 = (const float*)d_in[26];
    const float* Wm2 = (const float*)d_in[27];
    const float* bm2 = (const float*)d_in[28];
    float* out = (float*)d_out;

    float *p_h, *p_q, *p_k, *p_v, *p_z, *p_o, *p_o2, *p_h2, *p_f, *p_zb;
    cudaGetSymbolAddress((void**)&p_h,  g_h);
    cudaGetSymbolAddress((void**)&p_q,  g_q);
    cudaGetSymbolAddress((void**)&p_k,  g_k);
    cudaGetSymbolAddress((void**)&p_v,  g_v);
    cudaGetSymbolAddress((void**)&p_z,  g_z);
    cudaGetSymbolAddress((void**)&p_o,  g_o);
    cudaGetSymbolAddress((void**)&p_o2, g_o2);
    cudaGetSymbolAddress((void**)&p_h2, g_h2);
    cudaGetSymbolAddress((void**)&p_f,  g_f);
    cudaGetSymbolAddress((void**)&p_zb, g_zb);

    static const int FLASH_SMEM =
        (64 * SC_STRIDE) * 4 + 64 * 512 +
        (2112 + 2112 + 1024 + 1024 + 4096 + 128 + 256 + 64 + 448 + 16) * 4;
    cudaFuncSetAttribute(flash_attn_kernel,
                         cudaFuncAttributeMaxDynamicSharedMemorySize, FLASH_SMEM);

    const int SM128 = 3 * (A_FLOATS + 16 * 132) * 4;
    const int SM64  = 3 * (A_FLOATS + 16 * 68) * 4;
    cudaFuncSetAttribute(mma_gemm<128, false, true>,
                         cudaFuncAttributeMaxDynamicSharedMemorySize, SM128);
    cudaFuncSetAttribute(mma_gemm<128, true, false>,
                         cudaFuncAttributeMaxDynamicSharedMemorySize, SM128);
    cudaFuncSetAttribute(mma_gemm<64, false, true>,
                         cudaFuncAttributeMaxDynamicSharedMemorySize, SM64);

    didx_kernel<<<(cB * cL * cL) / 256, 256>>>(distances);
    embed_kernel<<<cBL, 256>>>(cell_types, cell_emb);
    prep_kernel<<<1, 448>>>(Kkr, Vqk, Vqr, Vkr);

    dim3 gQKV(cD / 128, cBL / 128, 3);      // 192 CTAs
    dim3 gSK (cD / 64, cBL / 128, 2);       // 256 CTAs (split-K O-proj / FF2)
    dim3 gFF1(cFF / 128, cBL / 128);        // 256 CTAs
    dim3 gFlash(cL / 64, cB * cH);          // 512 CTAs

    for (int ly = 0; ly < cNL; ly++) {
        const float* wq  = Wq + (size_t)ly * cD * cD;
        const float* wk  = Wk + (size_t)ly * cD * cD;
        const float* wv  = Wv + (size_t)ly * cD * cD;
        const float* wo  = Wo + (size_t)ly * cD * cD;
        const float* bqp = bq + (size_t)ly * cD;
        const float* bkp = bk + (size_t)ly * cD;
        const float* bvp = bv + (size_t)ly * cD;
        const float* bop = bo + (size_t)ly * cD;
        const float* w1  = W1 + (size_t)ly * cD * cFF;
        const float* b1p = b1 + (size_t)ly * cFF;
        const float* w2  = W2 + (size_t)ly * cFF * cD;
        const float* b2p = b2 + (size_t)ly * cD;
        const float* g1p  = g1  + (size_t)ly * cD;
        const float* be1p = be1 + (size_t)ly * cD;
        const float* g2p  = g2  + (size_t)ly * cD;
        const float* be2p = be2 + (size_t)ly * cD;

        GArgs aQKV = { p_h, wq, wk, wv, bqp, bkp, bvp, p_q, p_k, p_v };
        mma_gemm<128, false, true><<<gQKV, 256, SM128>>>(aQKV, cBL, cD, cD, cD, 0);

        qke_kernel<<<cBL, 256>>>(Kqk, Kqr);
        flash_attn_kernel<<<gFlash, 256, FLASH_SMEM>>>();

        // O-proj split-K=2: halves of K=512
        GArgs aO = { p_z, wo, wo + (size_t)256 * cD, wo,
                     bop, p_zb, p_zb, p_o, p_o2, p_o2 };
        mma_gemm<64, false, true><<<gSK, 256, SM64>>>(aO, cBL, cD, 256, cD, 256);
        ln3_kernel<<<cBL, 128>>>(p_h, p_o, p_o2, g1p, be1p, p_h2);

        GArgs aF1 = { p_h2, w1, 0, 0, b1p, 0, 0, p_f, 0, 0 };
        mma_gemm<128, true, false><<<gFF1, 256, SM128>>>(aF1, cBL, cFF, cD, cD, 0);

        // FF2 split-K=2: halves of K=2048
        GArgs aF2 = { p_f, w2, w2 + (size_t)1024 * cD, w2,
                      b2p, p_zb, p_zb, p_o, p_o2, p_o2 };
        mma_gemm<64, false, true><<<gSK, 256, SM64>>>(aF2, cBL, cD, 1024, cFF, 1024);
        ln3_kernel<<<cBL, 128>>>(p_h2, p_o, p_o2, g2p, be2p, p_h);
    }

    head_kernel<<<cB, 512>>>(Wm1, bm1, Wm2, bm2, out);
}